// round 14
// baseline (speedup 1.0000x reference)
#include <cuda_runtime.h>
#include <cuda_fp16.h>
#include <cstdint>

#define BN_EPS 1e-5f
#define NUM_GRAPHS 256

#define SLABB 132                      // B pair-slab stride in uint2 (132%16=4 -> 2-phase LDS.64)
#define BT_BYTES  (32 * SLABB * 8)     // 33792 B per 128-col W4 tile
#define BT_UINTS  (BT_BYTES / 4)       // 8448
#define W23P_BYTES (16 * SLABB * 8)    // 16896
#define W23P_UINTS (W23P_BYTES / 4)

// ---------------- device-global scratch ----------------------------------------
__device__ float g_W1f[3 * 64];
__device__ float g_b1f[64];
__device__ float g_b23f[128];
__device__ __align__(16) uint32_t g_W23pu[W23P_UINTS];     // W23 fp16 pair layout
__device__ __align__(16) uint32_t g_W4Tu[8 * BT_UINTS];    // W4 fp16 pair layout, 8 tiles

// ---------------- PTX helpers ---------------------------------------------------
__device__ __forceinline__ uint32_t smem_u32(const void* p) {
    uint32_t a;
    asm("{ .reg .u64 t; cvta.to.shared.u64 t, %1; cvt.u32.u64 %0, t; }" : "=r"(a) : "l"(p));
    return a;
}
#define MBAR_INIT(addr, cnt) \
    asm volatile("mbarrier.init.shared.b64 [%0], %1;" :: "r"(addr), "r"(cnt) : "memory")
#define MBAR_EXPECT_TX(addr, bytes) \
    asm volatile("mbarrier.arrive.expect_tx.shared.b64 _, [%0], %1;" :: "r"(addr), "r"(bytes) : "memory")
#define MBAR_WAIT(addr, phase) do { \
    asm volatile("{\n\t.reg .pred P;\n\tWL_%=:\n\t" \
        "mbarrier.try_wait.parity.acquire.cta.shared::cta.b64 P, [%0], %1, 0x989680;\n\t" \
        "@P bra.uni WD_%=;\n\tbra.uni WL_%=;\n\tWD_%=:\n\t}" \
        :: "r"(addr), "r"(phase) : "memory"); \
} while (0)
#define FENCE_ASYNC_SHARED() asm volatile("fence.proxy.async.shared::cta;" ::: "memory")

__device__ __forceinline__ void bulk_g2s(uint32_t dst, const void* src, uint32_t bytes, uint32_t mbar) {
    asm volatile("cp.async.bulk.shared::cta.global.mbarrier::complete_tx::bytes [%0], [%1], %2, [%3];"
                 :: "r"(dst), "l"(src), "r"(bytes), "r"(mbar) : "memory");
}

__device__ __forceinline__ uint32_t pack_h2(float lo, float hi) {
    __half2 h = __floats2half2_rn(lo, hi);
    uint32_t u;
    memcpy(&u, &h, 4);
    return u;
}

// fp16 mma: D(16x8,f32) += A(16x16,f16) * B(16x8,f16), row.col
__device__ __forceinline__ void mma_f16(float* c, const uint32_t* a, uint32_t b0, uint32_t b1) {
    asm volatile("mma.sync.aligned.m16n8k16.row.col.f32.f16.f16.f32 "
                 "{%0,%1,%2,%3}, {%4,%5,%6,%7}, {%8,%9}, {%0,%1,%2,%3};"
                 : "+f"(c[0]), "+f"(c[1]), "+f"(c[2]), "+f"(c[3])
                 : "r"(a[0]), "r"(a[1]), "r"(a[2]), "r"(a[3]), "r"(b0), "r"(b1));
}

__device__ __forceinline__ void ldsm_x4(uint32_t* r, uint32_t addr) {
    asm volatile("ldmatrix.sync.aligned.m8n8.x4.shared.b16 {%0,%1,%2,%3}, [%4];"
                 : "=r"(r[0]), "=r"(r[1]), "=r"(r[2]), "=r"(r[3]) : "r"(addr));
}

__device__ __forceinline__ unsigned encf(float f) {
    unsigned u = __float_as_uint(f);
    return (u & 0x80000000u) ? ~u : (u | 0x80000000u);
}

// ---------------- kernel 0: fold BN1; fuse W2@W3 (+BN3) -> fp16 pair layout -----
__global__ void prep_kernel(const float* __restrict__ W1, const float* __restrict__ b1,
                            const float* __restrict__ g1, const float* __restrict__ be1,
                            const float* __restrict__ m1, const float* __restrict__ v1,
                            const float* __restrict__ W2, const float* __restrict__ b2,
                            const float* __restrict__ W3, const float* __restrict__ b3,
                            const float* __restrict__ g3, const float* __restrict__ be3,
                            const float* __restrict__ m3, const float* __restrict__ v3)
{
    __shared__ float W2s[64 * 64];
    int t = threadIdx.x;  // 128
    for (int i = t; i < 64 * 64; i += 128) W2s[i] = W2[i];

    if (t < 64) {
        float s = g1[t] * rsqrtf(v1[t] + BN_EPS);
        for (int i = 0; i < 3; i++) g_W1f[i * 64 + t] = W1[i * 64 + t] * s;
        g_b1f[t] = (b1[t] - m1[t]) * s + be1[t];
    }
    float w3c[64];
    #pragma unroll
    for (int k = 0; k < 64; k++) w3c[k] = W3[k * 128 + t];
    __syncthreads();

    float s3 = g3[t] * rsqrtf(v3[t] + BN_EPS);
    float accb = 0.f;
    #pragma unroll
    for (int k = 0; k < 64; k++) accb = fmaf(b2[k], w3c[k], accb);
    g_b23f[t] = (accb + b3[t] - m3[t]) * s3 + be3[t];

    // W23[k][n=t] fused; pack k-pairs into fp16 pair layout
    for (int p = 0; p < 32; p++) {
        float a0 = 0.f, a1 = 0.f;
        #pragma unroll
        for (int kk = 0; kk < 64; kk++) {
            a0 = fmaf(W2s[(2 * p) * 64 + kk], w3c[kk], a0);
            a1 = fmaf(W2s[(2 * p + 1) * 64 + kk], w3c[kk], a1);
        }
        int k16 = p >> 3, pp = p & 7, kq = pp & 3, hh = pp >> 2;
        g_W23pu[(((k16 * 4 + kq) * SLABB) + t) * 2 + hh] = pack_h2(a0 * s3, a1 * s3);
    }
}

// ---------------- kernel 0b: W4 pack + output init (merged) ---------------------
__global__ void w4t_init_kernel(const float* __restrict__ W4,
                                unsigned* __restrict__ out_enc, int out_total) {
    int id = blockIdx.x * 256 + threadIdx.x;   // grid covers max(65536, out_total)
    if (id < out_total) out_enc[id] = 0x007FFFFFu;   // encf(-inf)
    if (id < 65536) {                           // kpair(64) x n(1024)
        int n = id & 1023, p = id >> 10;
        float v0 = W4[(size_t)(2 * p) * 1024 + n];
        float v1 = W4[(size_t)(2 * p + 1) * 1024 + n];
        int tile = n >> 7, nn = n & 127;
        int k16 = p >> 3, pp = p & 7, kq = pp & 3, hh = pp >> 2;
        g_W4Tu[(size_t)tile * BT_UINTS + (((k16 * 4 + kq) * SLABB) + nn) * 2 + hh] = pack_h2(v0, v1);
    }
}

// ---------------- fused kernel --------------------------------------------------
// 512 threads (16 warps), 128 points/CTA, 2 CTAs/SM -> 32 warps/SM.
// Warp tile: 32 rows x 32 cols (acc = 32 regs -> fits 64-reg cap).
__global__ void __launch_bounds__(512, 2)
fused_kernel(const float* __restrict__ x, const int* __restrict__ batch,
             unsigned* __restrict__ out_enc, int n)
{
    extern __shared__ float sm[];
    uint32_t* Asu = (uint32_t*)sm;         // h3 fp16, pitch 68 uints
    float* B0   = sm + 8704;
    float* B1   = sm + 17152;
    float* xs   = sm + 25600;
    float* w1s  = sm + 25984;
    float* b1s  = sm + 26176;
    float* b23s = sm + 26240;
    int*   sb   = (int*)(sm + 26368);

    uint32_t smem_base = smem_u32(sm);
    uint32_t barFull0 = smem_base + 26496 * 4;
    uint32_t barFull1 = barFull0 + 8;
    uint32_t bAddr[2] = { smem_base + 8704 * 4, smem_base + 17152 * 4 };
    float* Bbuf[2] = { B0, B1 };

    int t    = threadIdx.x;
    int wid  = t >> 5;
    int lane = t & 31;
    int p0   = blockIdx.x * 128;
    int r0 = lane >> 2, kq = lane & 3;
    int rgrp = wid >> 2;             // rows rgrp*32 .. +31
    int cgrp = wid & 3;              // cols cgrp*32 .. +31

    if (t == 0) { MBAR_INIT(barFull0, 1); MBAR_INIT(barFull1, 1); }
    __syncthreads();
    FENCE_ASYNC_SHARED();

    // B0 <- tile 0 immediately (hides under prologue + phase A); B1 <- W23p
    if (t == 0) {
        MBAR_EXPECT_TX(barFull0, BT_BYTES);
        bulk_g2s(bAddr[0], (const void*)g_W4Tu, BT_BYTES, barFull0);
        MBAR_EXPECT_TX(barFull1, W23P_BYTES);
        bulk_g2s(bAddr[1], (const void*)g_W23pu, W23P_BYTES, barFull1);
    }

    // ---- small loads ----
    if (t < 384) {
        int p = t / 3, c = t - p * 3;
        xs[c * 128 + p] = (p0 + p < n) ? x[(size_t)(p0 + p) * 3 + c] : 0.f;
    }
    if (t < 192) w1s[t] = g_W1f[t];
    if (t < 64)  b1s[t] = g_b1f[t];
    if (t < 128) b23s[t] = g_b23f[t];
    if (t < 128) {
        int p = p0 + t;
        sb[t] = (p < n) ? batch[p] : -1;
    }
    __syncthreads();

    // ---- phase A: h3 = relu(h1 @ W23 + b23); h1 in regs; fp16 mma --------------
    {
        float xr[4][3];
        #pragma unroll
        for (int mbk = 0; mbk < 2; mbk++)
            #pragma unroll
            for (int j = 0; j < 2; j++) {
                int row = rgrp * 32 + mbk * 16 + r0 + 8 * j;
                xr[mbk * 2 + j][0] = xs[row];
                xr[mbk * 2 + j][1] = xs[128 + row];
                xr[mbk * 2 + j][2] = xs[256 + row];
            }

        MBAR_WAIT(barFull1, 0);   // W23p ready in B1
        float acc[2][4][4];
        #pragma unroll
        for (int i = 0; i < 2; i++)
            #pragma unroll
            for (int j = 0; j < 4; j++)
                #pragma unroll
                for (int r = 0; r < 4; r++) acc[i][j][r] = 0.f;

        const uint2* Wp = (const uint2*)B1;
        #pragma unroll 1
        for (int k16 = 0; k16 < 4; k16++) {
            int kb = k16 * 16;
            int ks[4] = { kb + 2 * kq, kb + 2 * kq + 1, kb + 2 * kq + 8, kb + 2 * kq + 9 };
            float wv[4][4];
            #pragma unroll
            for (int q = 0; q < 4; q++) {
                wv[q][0] = w1s[ks[q]]; wv[q][1] = w1s[64 + ks[q]];
                wv[q][2] = w1s[128 + ks[q]]; wv[q][3] = b1s[ks[q]];
            }
            uint32_t a[2][4];
            #pragma unroll
            for (int mbk = 0; mbk < 2; mbk++) {
                float h[2][4];
                #pragma unroll
                for (int j = 0; j < 2; j++) {
                    const float* xv = xr[mbk * 2 + j];
                    #pragma unroll
                    for (int q = 0; q < 4; q++)
                        h[j][q] = fmaxf(fmaf(xv[0], wv[q][0],
                                   fmaf(xv[1], wv[q][1], fmaf(xv[2], wv[q][2], wv[q][3]))), 0.f);
                }
                a[mbk][0] = pack_h2(h[0][0], h[0][1]);
                a[mbk][1] = pack_h2(h[1][0], h[1][1]);
                a[mbk][2] = pack_h2(h[0][2], h[0][3]);
                a[mbk][3] = pack_h2(h[1][2], h[1][3]);
            }
            #pragma unroll
            for (int nbk = 0; nbk < 4; nbk++) {
                uint2 bv = Wp[(k16 * 4 + kq) * SLABB + cgrp * 32 + nbk * 8 + r0];
                #pragma unroll
                for (int mbk = 0; mbk < 2; mbk++)
                    mma_f16(acc[mbk][nbk], a[mbk], bv.x, bv.y);
            }
        }

        // epilogue: bias + relu -> half2, write As (conflict-free)
        #pragma unroll
        for (int mbk = 0; mbk < 2; mbk++) {
            int ra = rgrp * 32 + mbk * 16 + r0;
            #pragma unroll
            for (int nbk = 0; nbk < 4; nbk++) {
                int c0 = cgrp * 32 + nbk * 8 + kq * 2;
                float bb0 = b23s[c0], bb1 = b23s[c0 + 1];
                int cp = c0 >> 1;
                Asu[ra * 68 + cp] = pack_h2(fmaxf(acc[mbk][nbk][0] + bb0, 0.f),
                                            fmaxf(acc[mbk][nbk][1] + bb1, 0.f));
                Asu[(ra + 8) * 68 + cp] = pack_h2(fmaxf(acc[mbk][nbk][2] + bb0, 0.f),
                                                  fmaxf(acc[mbk][nbk][3] + bb1, 0.f));
            }
        }
    }
    __syncthreads();          // As visible; W23p reads done -> B1 free
    if (t == 0) {             // B1 <- tile 1 (hides under tile-0 MMAs)
        FENCE_ASYNC_SHARED();
        MBAR_EXPECT_TX(barFull1, BT_BYTES);
        bulk_g2s(bAddr[1], (const void*)(g_W4Tu + BT_UINTS), BT_BYTES, barFull1);
    }

    // ldmatrix per-lane addresses: lane l serves matrix (l>>3), local row (l&7)
    uint32_t aBase[2];
    {
        int mm = lane >> 3, ii = lane & 7;
        #pragma unroll
        for (int mbk = 0; mbk < 2; mbk++) {
            int row = rgrp * 32 + mbk * 16 + (mm & 1) * 8 + ii;
            aBase[mbk] = smem_base + (row * 68 + (mm >> 1) * 4) * 4;
        }
    }

    // ---- phase B: 8 N-tiles of 128 cols, fp16 mma, double-buffered -------------
    bool fast = (sb[0] >= 0) && (sb[0] == sb[127]);
    unsigned* outg = fast ? &out_enc[(size_t)sb[0] * 1024] : out_enc;

    #pragma unroll 1
    for (int nt = 0; nt < 8; nt++) {
        int buf = nt & 1;
        uint32_t barFull = buf ? barFull1 : barFull0;
        int parity = ((nt >> 1) ^ nt) & 1;
        MBAR_WAIT(barFull, parity);
        const uint2* Bp = (const uint2*)Bbuf[buf];

        float acc[2][4][4];
        #pragma unroll
        for (int i = 0; i < 2; i++)
            #pragma unroll
            for (int q = 0; q < 4; q++)
                #pragma unroll
                for (int r = 0; r < 4; r++) acc[i][q][r] = 0.f;

        #pragma unroll 2
        for (int k16 = 0; k16 < 8; k16++) {
            uint32_t a[2][4];
            #pragma unroll
            for (int mbk = 0; mbk < 2; mbk++)
                ldsm_x4(a[mbk], aBase[mbk] + k16 * 32);
            #pragma unroll
            for (int nbk = 0; nbk < 4; nbk++) {
                uint2 bv = Bp[(k16 * 4 + kq) * SLABB + cgrp * 32 + nbk * 8 + r0];
                #pragma unroll
                for (int mbk = 0; mbk < 2; mbk++)
                    mma_f16(acc[mbk][nbk], a[mbk], bv.x, bv.y);
            }
        }
        __syncthreads();   // all reads of B[buf] complete

        int n0 = nt * 128;
        if (fast) {
            if (t == 0 && nt + 2 < 8) {     // prefetch immediately after join
                FENCE_ASYNC_SHARED();
                MBAR_EXPECT_TX(barFull, BT_BYTES);
                bulk_g2s(bAddr[buf], (const void*)(g_W4Tu + (size_t)(nt + 2) * BT_UINTS),
                         BT_BYTES, barFull);
            }
            // warp-local column max over 32 rows + direct atomics
            #pragma unroll
            for (int nbk = 0; nbk < 4; nbk++) {
                float e = fmaxf(fmaxf(acc[0][nbk][0], acc[0][nbk][2]),
                                fmaxf(acc[1][nbk][0], acc[1][nbk][2]));
                float o = fmaxf(fmaxf(acc[0][nbk][1], acc[0][nbk][3]),
                                fmaxf(acc[1][nbk][1], acc[1][nbk][3]));
                #pragma unroll
                for (int d = 4; d <= 16; d <<= 1) {
                    e = fmaxf(e, __shfl_xor_sync(0xffffffffu, e, d));
                    o = fmaxf(o, __shfl_xor_sync(0xffffffffu, o, d));
                }
                if (r0 == 0) {
                    int c = n0 + cgrp * 32 + nbk * 8 + kq * 2;
                    atomicMax(&outg[c], encf(e));
                    atomicMax(&outg[c + 1], encf(o));
                }
            }
        } else {
            // slow path: stage 64 rows at a time into freed B[buf] (pitch 132)
            float* Cs = Bbuf[buf];
            #pragma unroll 1
            for (int h = 0; h < 2; h++) {
                if ((rgrp >> 1) == h) {
                    #pragma unroll
                    for (int mbk = 0; mbk < 2; mbk++) {
                        int rl = (rgrp & 1) * 32 + mbk * 16 + r0;
                        #pragma unroll
                        for (int nbk = 0; nbk < 4; nbk++) {
                            int c0 = cgrp * 32 + nbk * 8 + kq * 2;
                            *(float2*)&Cs[rl * 132 + c0] =
                                make_float2(acc[mbk][nbk][0], acc[mbk][nbk][1]);
                            *(float2*)&Cs[(rl + 8) * 132 + c0] =
                                make_float2(acc[mbk][nbk][2], acc[mbk][nbk][3]);
                        }
                    }
                }
                __syncthreads();
                {   // 512 threads: col = t&127, quarter = t>>7 scans 16 rows
                    int col = t & 127, qh = t >> 7;
                    int cur = -2; float best = 0.f;
                    unsigned* obase = &out_enc[n0 + col];
                    int mbase = h * 64 + qh * 16;
                    for (int m = 0; m < 16; m++) {
                        int g2 = sb[mbase + m];
                        float v = Cs[(qh * 16 + m) * 132 + col];
                        if (g2 != cur) {
                            if (cur >= 0) atomicMax(obase + (size_t)cur * 1024, encf(best));
                            cur = g2; best = v;
                        } else best = fmaxf(best, v);
                    }
                    if (cur >= 0) atomicMax(obase + (size_t)cur * 1024, encf(best));
                }
                __syncthreads();
            }
            if (t == 0 && nt + 2 < 8) {
                FENCE_ASYNC_SHARED();
                MBAR_EXPECT_TX(barFull, BT_BYTES);
                bulk_g2s(bAddr[buf], (const void*)(g_W4Tu + (size_t)(nt + 2) * BT_UINTS),
                         BT_BYTES, barFull);
            }
        }
    }
}

// ---------------- decode --------------------------------------------------------
__global__ void decode_out(float* out, const float* __restrict__ b4, int total) {
    int i = blockIdx.x * 256 + threadIdx.x;
    if (i < total) {
        unsigned u = ((unsigned*)out)[i];
        unsigned d = (u & 0x80000000u) ? (u ^ 0x80000000u) : ~u;
        out[i] = __uint_as_float(d) + b4[i & 1023];
    }
}

// ---------------- launch -------------------------------------------------------
extern "C" void kernel_launch(void* const* d_in, const int* in_sizes, int n_in,
                              void* d_out, int out_size)
{
    const float* x     = (const float*)d_in[0];
    const int*   batch = (const int*)  d_in[1];
    const float* W1  = (const float*)d_in[2];
    const float* b1  = (const float*)d_in[3];
    const float* g1  = (const float*)d_in[4];
    const float* be1 = (const float*)d_in[5];
    const float* m1  = (const float*)d_in[6];
    const float* v1  = (const float*)d_in[7];
    const float* W2  = (const float*)d_in[8];
    const float* b2  = (const float*)d_in[9];
    const float* W3  = (const float*)d_in[10];
    const float* b3  = (const float*)d_in[11];
    const float* g3  = (const float*)d_in[12];
    const float* be3 = (const float*)d_in[13];
    const float* m3  = (const float*)d_in[14];
    const float* v3  = (const float*)d_in[15];
    const float* W4  = (const float*)d_in[16];
    const float* b4  = (const float*)d_in[17];

    int n  = in_sizes[0] / 3;
    int NT = (n + 127) / 128;

    size_t smB = 106000;   // -> 2 CTAs/SM
    cudaFuncSetAttribute(fused_kernel, cudaFuncAttributeMaxDynamicSharedMemorySize, (int)smB);

    prep_kernel<<<1, 128>>>(W1, b1, g1, be1, m1, v1, W2, b2, W3, b3, g3, be3, m3, v3);

    int initN = out_size > 65536 ? out_size : 65536;
    w4t_init_kernel<<<(initN + 255) / 256, 256>>>(W4, (unsigned*)d_out, out_size);

    fused_kernel<<<NT, 512, smB>>>(x, batch, (unsigned*)d_out, n);

    decode_out<<<(out_size + 255) / 256, 256>>>((float*)d_out, b4, out_size);
}

// round 15
// speedup vs baseline: 1.1037x; 1.1037x over previous
#include <cuda_runtime.h>
#include <cuda_fp16.h>
#include <cstdint>

#define BN_EPS 1e-5f
#define NUM_GRAPHS 256

#define SLABB 132                      // B pair-slab stride in uint2 (132%16=4 -> 2-phase LDS.64)
#define BT_BYTES  (32 * SLABB * 8)     // 33792 B per 128-col W4 tile
#define BT_UINTS  (BT_BYTES / 4)       // 8448
#define W23P_BYTES (16 * SLABB * 8)    // 16896
#define W23P_UINTS (W23P_BYTES / 4)

// ---------------- device-global scratch ----------------------------------------
__device__ float g_W1f[3 * 64];
__device__ float g_b1f[64];
__device__ float g_b23f[128];
__device__ __align__(16) uint32_t g_W23pu[W23P_UINTS];     // W23 fp16 pair layout
__device__ __align__(16) uint32_t g_W4Tu[8 * BT_UINTS];    // W4 fp16 pair layout, 8 tiles

// ---------------- PTX helpers ---------------------------------------------------
__device__ __forceinline__ uint32_t smem_u32(const void* p) {
    uint32_t a;
    asm("{ .reg .u64 t; cvta.to.shared.u64 t, %1; cvt.u32.u64 %0, t; }" : "=r"(a) : "l"(p));
    return a;
}
#define MBAR_INIT(addr, cnt) \
    asm volatile("mbarrier.init.shared.b64 [%0], %1;" :: "r"(addr), "r"(cnt) : "memory")
#define MBAR_EXPECT_TX(addr, bytes) \
    asm volatile("mbarrier.arrive.expect_tx.shared.b64 _, [%0], %1;" :: "r"(addr), "r"(bytes) : "memory")
#define MBAR_WAIT(addr, phase) do { \
    asm volatile("{\n\t.reg .pred P;\n\tWL_%=:\n\t" \
        "mbarrier.try_wait.parity.acquire.cta.shared::cta.b64 P, [%0], %1, 0x989680;\n\t" \
        "@P bra.uni WD_%=;\n\tbra.uni WL_%=;\n\tWD_%=:\n\t}" \
        :: "r"(addr), "r"(phase) : "memory"); \
} while (0)
#define FENCE_ASYNC_SHARED() asm volatile("fence.proxy.async.shared::cta;" ::: "memory")

__device__ __forceinline__ void bulk_g2s(uint32_t dst, const void* src, uint32_t bytes, uint32_t mbar) {
    asm volatile("cp.async.bulk.shared::cta.global.mbarrier::complete_tx::bytes [%0], [%1], %2, [%3];"
                 :: "r"(dst), "l"(src), "r"(bytes), "r"(mbar) : "memory");
}

__device__ __forceinline__ uint32_t pack_h2(float lo, float hi) {
    __half2 h = __floats2half2_rn(lo, hi);
    uint32_t u;
    memcpy(&u, &h, 4);
    return u;
}

// fp16 mma: D(16x8,f32) += A(16x16,f16) * B(16x8,f16), row.col
__device__ __forceinline__ void mma_f16(float* c, const uint32_t* a, uint32_t b0, uint32_t b1) {
    asm volatile("mma.sync.aligned.m16n8k16.row.col.f32.f16.f16.f32 "
                 "{%0,%1,%2,%3}, {%4,%5,%6,%7}, {%8,%9}, {%0,%1,%2,%3};"
                 : "+f"(c[0]), "+f"(c[1]), "+f"(c[2]), "+f"(c[3])
                 : "r"(a[0]), "r"(a[1]), "r"(a[2]), "r"(a[3]), "r"(b0), "r"(b1));
}

__device__ __forceinline__ void ldsm_x4(uint32_t* r, uint32_t addr) {
    asm volatile("ldmatrix.sync.aligned.m8n8.x4.shared.b16 {%0,%1,%2,%3}, [%4];"
                 : "=r"(r[0]), "=r"(r[1]), "=r"(r[2]), "=r"(r[3]) : "r"(addr));
}

__device__ __forceinline__ unsigned encf(float f) {
    unsigned u = __float_as_uint(f);
    return (u & 0x80000000u) ? ~u : (u | 0x80000000u);
}

// ---------------- kernel 0: fold BN1; fuse W2@W3 (+BN3) -> fp16 pair layout -----
__global__ void prep_kernel(const float* __restrict__ W1, const float* __restrict__ b1,
                            const float* __restrict__ g1, const float* __restrict__ be1,
                            const float* __restrict__ m1, const float* __restrict__ v1,
                            const float* __restrict__ W2, const float* __restrict__ b2,
                            const float* __restrict__ W3, const float* __restrict__ b3,
                            const float* __restrict__ g3, const float* __restrict__ be3,
                            const float* __restrict__ m3, const float* __restrict__ v3)
{
    __shared__ float W2s[64 * 64];
    int t = threadIdx.x;  // 128
    for (int i = t; i < 64 * 64; i += 128) W2s[i] = W2[i];

    if (t < 64) {
        float s = g1[t] * rsqrtf(v1[t] + BN_EPS);
        for (int i = 0; i < 3; i++) g_W1f[i * 64 + t] = W1[i * 64 + t] * s;
        g_b1f[t] = (b1[t] - m1[t]) * s + be1[t];
    }
    float w3c[64];
    #pragma unroll
    for (int k = 0; k < 64; k++) w3c[k] = W3[k * 128 + t];
    __syncthreads();

    float s3 = g3[t] * rsqrtf(v3[t] + BN_EPS);
    float accb = 0.f;
    #pragma unroll
    for (int k = 0; k < 64; k++) accb = fmaf(b2[k], w3c[k], accb);
    g_b23f[t] = (accb + b3[t] - m3[t]) * s3 + be3[t];

    // W23[k][n=t] fused; pack k-pairs into fp16 pair layout
    for (int p = 0; p < 32; p++) {
        float a0 = 0.f, a1 = 0.f;
        #pragma unroll
        for (int kk = 0; kk < 64; kk++) {
            a0 = fmaf(W2s[(2 * p) * 64 + kk], w3c[kk], a0);
            a1 = fmaf(W2s[(2 * p + 1) * 64 + kk], w3c[kk], a1);
        }
        int k16 = p >> 3, pp = p & 7, kq = pp & 3, hh = pp >> 2;
        g_W23pu[(((k16 * 4 + kq) * SLABB) + t) * 2 + hh] = pack_h2(a0 * s3, a1 * s3);
    }
}

// ---------------- kernel 0b: W4 pack + output init (merged) ---------------------
__global__ void w4t_init_kernel(const float* __restrict__ W4,
                                unsigned* __restrict__ out_enc, int out_total) {
    int id = blockIdx.x * 256 + threadIdx.x;   // grid covers max(65536, out_total)
    if (id < out_total) out_enc[id] = 0x007FFFFFu;   // encf(-inf)
    if (id < 65536) {                           // kpair(64) x n(1024)
        int n = id & 1023, p = id >> 10;
        float v0 = W4[(size_t)(2 * p) * 1024 + n];
        float v1 = W4[(size_t)(2 * p + 1) * 1024 + n];
        int tile = n >> 7, nn = n & 127;
        int k16 = p >> 3, pp = p & 7, kq = pp & 3, hh = pp >> 2;
        g_W4Tu[(size_t)tile * BT_UINTS + (((k16 * 4 + kq) * SLABB) + nn) * 2 + hh] = pack_h2(v0, v1);
    }
}

// ---------------- fused kernel --------------------------------------------------
// 256 threads (8 warps), 128 points/CTA, 2 CTAs/SM.
__global__ void __launch_bounds__(256, 2)
fused_kernel(const float* __restrict__ x, const int* __restrict__ batch,
             unsigned* __restrict__ out_enc, int n)
{
    extern __shared__ float sm[];
    uint32_t* Asu = (uint32_t*)sm;         // h3 fp16, pitch 68 uints
    float* B0   = sm + 8704;
    float* B1   = sm + 17152;
    float* xs   = sm + 25600;
    float* w1s  = sm + 25984;
    float* b1s  = sm + 26176;
    float* b23s = sm + 26240;
    int*   sb   = (int*)(sm + 26368);

    uint32_t smem_base = smem_u32(sm);
    uint32_t barFull0 = smem_base + 26496 * 4;
    uint32_t barFull1 = barFull0 + 8;
    uint32_t bAddr[2] = { smem_base + 8704 * 4, smem_base + 17152 * 4 };
    float* Bbuf[2] = { B0, B1 };

    int t    = threadIdx.x;
    int wid  = t >> 5;
    int lane = t & 31;
    int p0   = blockIdx.x * 128;
    int r0 = lane >> 2, kq = lane & 3;
    int mhalf = wid >> 2;            // rows mhalf*64 .. +63
    int nblk  = wid & 3;             // cols nblk*32 .. +31

    if (t == 0) { MBAR_INIT(barFull0, 1); MBAR_INIT(barFull1, 1); }
    __syncthreads();
    FENCE_ASYNC_SHARED();

    // B0 <- tile 0 immediately (hides under prologue + phase A); B1 <- W23p
    if (t == 0) {
        MBAR_EXPECT_TX(barFull0, BT_BYTES);
        bulk_g2s(bAddr[0], (const void*)g_W4Tu, BT_BYTES, barFull0);
        MBAR_EXPECT_TX(barFull1, W23P_BYTES);
        bulk_g2s(bAddr[1], (const void*)g_W23pu, W23P_BYTES, barFull1);
    }

    // ---- small loads ----
    for (int i = t; i < 384; i += 256) {
        int p = i / 3, c = i - p * 3;
        xs[c * 128 + p] = (p0 + p < n) ? x[(size_t)(p0 + p) * 3 + c] : 0.f;
    }
    if (t < 192) w1s[t] = g_W1f[t];
    if (t < 64)  b1s[t] = g_b1f[t];
    if (t < 128) b23s[t] = g_b23f[t];
    if (t < 128) {
        int p = p0 + t;
        sb[t] = (p < n) ? batch[p] : -1;
    }
    __syncthreads();

    // ---- phase A: h3 = relu(h1 @ W23 + b23); h1 in regs; fp16 mma --------------
    {
        float xr[8][3];
        #pragma unroll
        for (int mbk = 0; mbk < 4; mbk++)
            #pragma unroll
            for (int j = 0; j < 2; j++) {
                int row = mhalf * 64 + mbk * 16 + r0 + 8 * j;
                xr[mbk * 2 + j][0] = xs[row];
                xr[mbk * 2 + j][1] = xs[128 + row];
                xr[mbk * 2 + j][2] = xs[256 + row];
            }

        MBAR_WAIT(barFull1, 0);   // W23p ready in B1
        float acc[4][4][4];
        #pragma unroll
        for (int i = 0; i < 4; i++)
            #pragma unroll
            for (int j = 0; j < 4; j++)
                #pragma unroll
                for (int r = 0; r < 4; r++) acc[i][j][r] = 0.f;

        const uint2* Wp = (const uint2*)B1;
        #pragma unroll 1
        for (int k16 = 0; k16 < 4; k16++) {
            int kb = k16 * 16;
            int ks[4] = { kb + 2 * kq, kb + 2 * kq + 1, kb + 2 * kq + 8, kb + 2 * kq + 9 };
            float wv[4][4];
            #pragma unroll
            for (int q = 0; q < 4; q++) {
                wv[q][0] = w1s[ks[q]]; wv[q][1] = w1s[64 + ks[q]];
                wv[q][2] = w1s[128 + ks[q]]; wv[q][3] = b1s[ks[q]];
            }
            uint32_t a[4][4];
            #pragma unroll
            for (int mbk = 0; mbk < 4; mbk++) {
                float h[2][4];
                #pragma unroll
                for (int j = 0; j < 2; j++) {
                    const float* xv = xr[mbk * 2 + j];
                    #pragma unroll
                    for (int q = 0; q < 4; q++)
                        h[j][q] = fmaxf(fmaf(xv[0], wv[q][0],
                                   fmaf(xv[1], wv[q][1], fmaf(xv[2], wv[q][2], wv[q][3]))), 0.f);
                }
                a[mbk][0] = pack_h2(h[0][0], h[0][1]);
                a[mbk][1] = pack_h2(h[1][0], h[1][1]);
                a[mbk][2] = pack_h2(h[0][2], h[0][3]);
                a[mbk][3] = pack_h2(h[1][2], h[1][3]);
            }
            #pragma unroll
            for (int nbk = 0; nbk < 4; nbk++) {
                uint2 bv = Wp[(k16 * 4 + kq) * SLABB + nblk * 32 + nbk * 8 + r0];
                #pragma unroll
                for (int mbk = 0; mbk < 4; mbk++)
                    mma_f16(acc[mbk][nbk], a[mbk], bv.x, bv.y);
            }
        }

        // epilogue: bias + relu -> half2, write As (conflict-free)
        #pragma unroll
        for (int mbk = 0; mbk < 4; mbk++) {
            int ra = mhalf * 64 + mbk * 16 + r0;
            #pragma unroll
            for (int nbk = 0; nbk < 4; nbk++) {
                int c0 = nblk * 32 + nbk * 8 + kq * 2;
                float bb0 = b23s[c0], bb1 = b23s[c0 + 1];
                int cp = c0 >> 1;
                Asu[ra * 68 + cp] = pack_h2(fmaxf(acc[mbk][nbk][0] + bb0, 0.f),
                                            fmaxf(acc[mbk][nbk][1] + bb1, 0.f));
                Asu[(ra + 8) * 68 + cp] = pack_h2(fmaxf(acc[mbk][nbk][2] + bb0, 0.f),
                                                  fmaxf(acc[mbk][nbk][3] + bb1, 0.f));
            }
        }
    }
    __syncthreads();          // As visible; W23p reads done -> B1 free
    if (t == 0) {             // B1 <- tile 1 (hides under tile-0 MMAs)
        FENCE_ASYNC_SHARED();
        MBAR_EXPECT_TX(barFull1, BT_BYTES);
        bulk_g2s(bAddr[1], (const void*)(g_W4Tu + BT_UINTS), BT_BYTES, barFull1);
    }

    // ldmatrix per-lane addresses: lane l serves matrix (l>>3), local row (l&7)
    uint32_t aBase[4];
    {
        int mm = lane >> 3, ii = lane & 7;
        #pragma unroll
        for (int mbk = 0; mbk < 4; mbk++) {
            int row = mhalf * 64 + mbk * 16 + (mm & 1) * 8 + ii;
            aBase[mbk] = smem_base + (row * 68 + (mm >> 1) * 4) * 4;
        }
    }

    // ---- phase B: 8 N-tiles of 128 cols, fp16 mma, double-buffered -------------
    bool fast = (sb[0] >= 0) && (sb[0] == sb[127]);
    unsigned* outg = fast ? &out_enc[(size_t)sb[0] * 1024] : out_enc;

    #pragma unroll 1
    for (int nt = 0; nt < 8; nt++) {
        int buf = nt & 1;
        uint32_t barFull = buf ? barFull1 : barFull0;
        int parity = ((nt >> 1) ^ nt) & 1;
        MBAR_WAIT(barFull, parity);
        const uint2* Bp = (const uint2*)Bbuf[buf];

        float acc[4][4][4];
        #pragma unroll
        for (int i = 0; i < 4; i++)
            #pragma unroll
            for (int q = 0; q < 4; q++)
                #pragma unroll
                for (int r = 0; r < 4; r++) acc[i][q][r] = 0.f;

        #pragma unroll 2
        for (int k16 = 0; k16 < 8; k16++) {
            uint32_t a[4][4];
            #pragma unroll
            for (int mbk = 0; mbk < 4; mbk++)
                ldsm_x4(a[mbk], aBase[mbk] + k16 * 32);
            #pragma unroll
            for (int nbk = 0; nbk < 4; nbk++) {
                uint2 bv = Bp[(k16 * 4 + kq) * SLABB + nblk * 32 + nbk * 8 + r0];
                #pragma unroll
                for (int mbk = 0; mbk < 4; mbk++)
                    mma_f16(acc[mbk][nbk], a[mbk], bv.x, bv.y);
            }
        }
        __syncthreads();   // all reads of B[buf] complete

        int n0 = nt * 128;
        if (fast) {
            if (t == 0 && nt + 2 < 8) {     // prefetch immediately after join
                FENCE_ASYNC_SHARED();
                MBAR_EXPECT_TX(barFull, BT_BYTES);
                bulk_g2s(bAddr[buf], (const void*)(g_W4Tu + (size_t)(nt + 2) * BT_UINTS),
                         BT_BYTES, barFull);
            }
            #pragma unroll
            for (int nbk = 0; nbk < 4; nbk++) {
                float e = fmaxf(acc[0][nbk][0], acc[0][nbk][2]);
                float o = fmaxf(acc[0][nbk][1], acc[0][nbk][3]);
                #pragma unroll
                for (int mbk = 1; mbk < 4; mbk++) {
                    e = fmaxf(e, fmaxf(acc[mbk][nbk][0], acc[mbk][nbk][2]));
                    o = fmaxf(o, fmaxf(acc[mbk][nbk][1], acc[mbk][nbk][3]));
                }
                #pragma unroll
                for (int d = 4; d <= 16; d <<= 1) {
                    e = fmaxf(e, __shfl_xor_sync(0xffffffffu, e, d));
                    o = fmaxf(o, __shfl_xor_sync(0xffffffffu, o, d));
                }
                if (r0 == 0) {
                    int c = n0 + nblk * 32 + nbk * 8 + kq * 2;
                    atomicMax(&outg[c], encf(e));
                    atomicMax(&outg[c + 1], encf(o));
                }
            }
        } else {
            // slow path: stage 64 rows at a time into freed B[buf] (pitch 132)
            float* Cs = Bbuf[buf];
            #pragma unroll 1
            for (int h = 0; h < 2; h++) {
                if (mhalf == h) {
                    #pragma unroll
                    for (int mbk = 0; mbk < 4; mbk++) {
                        int rl = mbk * 16 + r0;
                        #pragma unroll
                        for (int nbk = 0; nbk < 4; nbk++) {
                            int c0 = nblk * 32 + nbk * 8 + kq * 2;
                            *(float2*)&Cs[rl * 132 + c0] =
                                make_float2(acc[mbk][nbk][0], acc[mbk][nbk][1]);
                            *(float2*)&Cs[(rl + 8) * 132 + c0] =
                                make_float2(acc[mbk][nbk][2], acc[mbk][nbk][3]);
                        }
                    }
                }
                __syncthreads();
                {   // 256 threads: col = t&127, quarter = t>>7 scans 32 rows
                    int col = t & 127, qh = t >> 7;
                    int cur = -2; float best = 0.f;
                    unsigned* obase = &out_enc[n0 + col];
                    int mbase = h * 64 + qh * 32;
                    for (int m = 0; m < 32; m++) {
                        int g2 = sb[mbase + m];
                        float v = Cs[(qh * 32 + m) * 132 + col];
                        if (g2 != cur) {
                            if (cur >= 0) atomicMax(obase + (size_t)cur * 1024, encf(best));
                            cur = g2; best = v;
                        } else best = fmaxf(best, v);
                    }
                    if (cur >= 0) atomicMax(obase + (size_t)cur * 1024, encf(best));
                }
                __syncthreads();
            }
            if (t == 0 && nt + 2 < 8) {
                FENCE_ASYNC_SHARED();
                MBAR_EXPECT_TX(barFull, BT_BYTES);
                bulk_g2s(bAddr[buf], (const void*)(g_W4Tu + (size_t)(nt + 2) * BT_UINTS),
                         BT_BYTES, barFull);
            }
        }
    }
}

// ---------------- decode --------------------------------------------------------
__global__ void decode_out(float* out, const float* __restrict__ b4, int total) {
    int i = blockIdx.x * 256 + threadIdx.x;
    if (i < total) {
        unsigned u = ((unsigned*)out)[i];
        unsigned d = (u & 0x80000000u) ? (u ^ 0x80000000u) : ~u;
        out[i] = __uint_as_float(d) + b4[i & 1023];
    }
}

// ---------------- launch -------------------------------------------------------
extern "C" void kernel_launch(void* const* d_in, const int* in_sizes, int n_in,
                              void* d_out, int out_size)
{
    const float* x     = (const float*)d_in[0];
    const int*   batch = (const int*)  d_in[1];
    const float* W1  = (const float*)d_in[2];
    const float* b1  = (const float*)d_in[3];
    const float* g1  = (const float*)d_in[4];
    const float* be1 = (const float*)d_in[5];
    const float* m1  = (const float*)d_in[6];
    const float* v1  = (const float*)d_in[7];
    const float* W2  = (const float*)d_in[8];
    const float* b2  = (const float*)d_in[9];
    const float* W3  = (const float*)d_in[10];
    const float* b3  = (const float*)d_in[11];
    const float* g3  = (const float*)d_in[12];
    const float* be3 = (const float*)d_in[13];
    const float* m3  = (const float*)d_in[14];
    const float* v3  = (const float*)d_in[15];
    const float* W4  = (const float*)d_in[16];
    const float* b4  = (const float*)d_in[17];

    int n  = in_sizes[0] / 3;
    int NT = (n + 127) / 128;

    size_t smB = 106000;   // -> 2 CTAs/SM
    cudaFuncSetAttribute(fused_kernel, cudaFuncAttributeMaxDynamicSharedMemorySize, (int)smB);

    prep_kernel<<<1, 128>>>(W1, b1, g1, be1, m1, v1, W2, b2, W3, b3, g3, be3, m3, v3);

    int initN = out_size > 65536 ? out_size : 65536;
    w4t_init_kernel<<<(initN + 255) / 256, 256>>>(W4, (unsigned*)d_out, out_size);

    fused_kernel<<<NT, 256, smB>>>(x, batch, (unsigned*)d_out, n);

    decode_out<<<(out_size + 255) / 256, 256>>>((float*)d_out, b4, out_size);
}

// round 17
// speedup vs baseline: 1.1078x; 1.0037x over previous
#include <cuda_runtime.h>
#include <cuda_fp16.h>
#include <cstdint>

#define BN_EPS 1e-5f
#define NUM_GRAPHS 256

#define SLABB 132                      // B pair-slab stride in uint2 (132%16=4 -> 2-phase LDS.64)
#define BT_BYTES  (32 * SLABB * 8)     // 33792 B per 128-col W4 tile
#define BT_UINTS  (BT_BYTES / 4)       // 8448
#define W23P_BYTES (16 * SLABB * 8)    // 16896
#define W23P_UINTS (W23P_BYTES / 4)

// ---------------- device-global scratch ----------------------------------------
__device__ float g_W1f[3 * 64];
__device__ float g_b1f[64];
__device__ float g_b23f[128];
__device__ __align__(16) uint32_t g_W23pu[W23P_UINTS];     // W23 fp16 pair layout
__device__ __align__(16) uint32_t g_W4Tu[8 * BT_UINTS];    // W4 fp16 pair layout, 8 tiles

// ---------------- PTX helpers ---------------------------------------------------
__device__ __forceinline__ uint32_t smem_u32(const void* p) {
    uint32_t a;
    asm("{ .reg .u64 t; cvta.to.shared.u64 t, %1; cvt.u32.u64 %0, t; }" : "=r"(a) : "l"(p));
    return a;
}
#define MBAR_INIT(addr, cnt) \
    asm volatile("mbarrier.init.shared.b64 [%0], %1;" :: "r"(addr), "r"(cnt) : "memory")
#define MBAR_EXPECT_TX(addr, bytes) \
    asm volatile("mbarrier.arrive.expect_tx.shared.b64 _, [%0], %1;" :: "r"(addr), "r"(bytes) : "memory")
#define MBAR_WAIT(addr, phase) do { \
    asm volatile("{\n\t.reg .pred P;\n\tWL_%=:\n\t" \
        "mbarrier.try_wait.parity.acquire.cta.shared::cta.b64 P, [%0], %1, 0x989680;\n\t" \
        "@P bra.uni WD_%=;\n\tbra.uni WL_%=;\n\tWD_%=:\n\t}" \
        :: "r"(addr), "r"(phase) : "memory"); \
} while (0)
#define FENCE_ASYNC_SHARED() asm volatile("fence.proxy.async.shared::cta;" ::: "memory")

__device__ __forceinline__ void bulk_g2s(uint32_t dst, const void* src, uint32_t bytes, uint32_t mbar) {
    asm volatile("cp.async.bulk.shared::cta.global.mbarrier::complete_tx::bytes [%0], [%1], %2, [%3];"
                 :: "r"(dst), "l"(src), "r"(bytes), "r"(mbar) : "memory");
}

__device__ __forceinline__ uint32_t pack_h2(float lo, float hi) {
    __half2 h = __floats2half2_rn(lo, hi);
    uint32_t u;
    memcpy(&u, &h, 4);
    return u;
}

// fp16 mma: D(16x8,f32) += A(16x16,f16) * B(16x8,f16), row.col
__device__ __forceinline__ void mma_f16(float* c, const uint32_t* a, uint32_t b0, uint32_t b1) {
    asm volatile("mma.sync.aligned.m16n8k16.row.col.f32.f16.f16.f32 "
                 "{%0,%1,%2,%3}, {%4,%5,%6,%7}, {%8,%9}, {%0,%1,%2,%3};"
                 : "+f"(c[0]), "+f"(c[1]), "+f"(c[2]), "+f"(c[3])
                 : "r"(a[0]), "r"(a[1]), "r"(a[2]), "r"(a[3]), "r"(b0), "r"(b1));
}

__device__ __forceinline__ void ldsm_x4(uint32_t* r, uint32_t addr) {
    asm volatile("ldmatrix.sync.aligned.m8n8.x4.shared.b16 {%0,%1,%2,%3}, [%4];"
                 : "=r"(r[0]), "=r"(r[1]), "=r"(r[2]), "=r"(r[3]) : "r"(addr));
}

__device__ __forceinline__ unsigned encf(float f) {
    unsigned u = __float_as_uint(f);
    return (u & 0x80000000u) ? ~u : (u | 0x80000000u);
}

// ---------------- kernel 0: fold BN1; fuse W2@W3 (+BN3) -> fp16 pair layout -----
__global__ void prep_kernel(const float* __restrict__ W1, const float* __restrict__ b1,
                            const float* __restrict__ g1, const float* __restrict__ be1,
                            const float* __restrict__ m1, const float* __restrict__ v1,
                            const float* __restrict__ W2, const float* __restrict__ b2,
                            const float* __restrict__ W3, const float* __restrict__ b3,
                            const float* __restrict__ g3, const float* __restrict__ be3,
                            const float* __restrict__ m3, const float* __restrict__ v3)
{
    __shared__ float W2s[64 * 64];
    int t = threadIdx.x;  // 128
    for (int i = t; i < 64 * 64; i += 128) W2s[i] = W2[i];

    if (t < 64) {
        float s = g1[t] * rsqrtf(v1[t] + BN_EPS);
        for (int i = 0; i < 3; i++) g_W1f[i * 64 + t] = W1[i * 64 + t] * s;
        g_b1f[t] = (b1[t] - m1[t]) * s + be1[t];
    }
    float w3c[64];
    #pragma unroll
    for (int k = 0; k < 64; k++) w3c[k] = W3[k * 128 + t];
    __syncthreads();

    float s3 = g3[t] * rsqrtf(v3[t] + BN_EPS);
    float accb = 0.f;
    #pragma unroll
    for (int k = 0; k < 64; k++) accb = fmaf(b2[k], w3c[k], accb);
    g_b23f[t] = (accb + b3[t] - m3[t]) * s3 + be3[t];

    // W23[k][n=t] fused; pack k-pairs into fp16 pair layout
    for (int p = 0; p < 32; p++) {
        float a0 = 0.f, a1 = 0.f;
        #pragma unroll
        for (int kk = 0; kk < 64; kk++) {
            a0 = fmaf(W2s[(2 * p) * 64 + kk], w3c[kk], a0);
            a1 = fmaf(W2s[(2 * p + 1) * 64 + kk], w3c[kk], a1);
        }
        int k16 = p >> 3, pp = p & 7, kq = pp & 3, hh = pp >> 2;
        g_W23pu[(((k16 * 4 + kq) * SLABB) + t) * 2 + hh] = pack_h2(a0 * s3, a1 * s3);
    }
}

// ---------------- kernel 0b: W4 pack + output init (merged) ---------------------
__global__ void w4t_init_kernel(const float* __restrict__ W4,
                                unsigned* __restrict__ out_enc, int out_total) {
    int id = blockIdx.x * 256 + threadIdx.x;   // grid covers max(65536, out_total)
    if (id < out_total) out_enc[id] = 0x007FFFFFu;   // encf(-inf)
    if (id < 65536) {                           // kpair(64) x n(1024)
        int n = id & 1023, p = id >> 10;
        float v0 = W4[(size_t)(2 * p) * 1024 + n];
        float v1 = W4[(size_t)(2 * p + 1) * 1024 + n];
        int tile = n >> 7, nn = n & 127;
        int k16 = p >> 3, pp = p & 7, kq = pp & 3, hh = pp >> 2;
        g_W4Tu[(size_t)tile * BT_UINTS + (((k16 * 4 + kq) * SLABB) + nn) * 2 + hh] = pack_h2(v0, v1);
    }
}

// ---------------- fused kernel --------------------------------------------------
// 256 threads (8 warps), 128 points/CTA, 2 CTAs/SM.
// W23p overlays the As region during phase A, freeing BOTH B buffers for
// tile-0/tile-1 loads issued at kernel start (deeper prefetch pipeline).
__global__ void __launch_bounds__(256, 2)
fused_kernel(const float* __restrict__ x, const int* __restrict__ batch,
             unsigned* __restrict__ out_enc, int n)
{
    extern __shared__ float sm[];
    uint32_t* Asu = (uint32_t*)sm;         // h3 fp16, pitch 68 uints (also W23p overlay)
    float* B0   = sm + 8704;
    float* B1   = sm + 17152;
    float* xs   = sm + 25600;
    float* w1s  = sm + 25984;
    float* b1s  = sm + 26176;
    float* b23s = sm + 26240;
    int*   sb   = (int*)(sm + 26368);

    uint32_t smem_base = smem_u32(sm);
    uint32_t barFull0 = smem_base + 26496 * 4;
    uint32_t barFull1 = barFull0 + 8;
    uint32_t barW     = barFull0 + 16;
    uint32_t bAddr[2] = { smem_base + 8704 * 4, smem_base + 17152 * 4 };
    float* Bbuf[2] = { B0, B1 };

    int t    = threadIdx.x;
    int wid  = t >> 5;
    int lane = t & 31;
    int p0   = blockIdx.x * 128;
    int r0 = lane >> 2, kq = lane & 3;
    int mhalf = wid >> 2;            // rows mhalf*64 .. +63
    int nblk  = wid & 3;             // cols nblk*32 .. +31

    if (t == 0) { MBAR_INIT(barFull0, 1); MBAR_INIT(barFull1, 1); MBAR_INIT(barW, 1); }
    __syncthreads();
    FENCE_ASYNC_SHARED();

    // All three loads issued at kernel start: tiles 0,1 + W23p (into As overlay)
    if (t == 0) {
        MBAR_EXPECT_TX(barFull0, BT_BYTES);
        bulk_g2s(bAddr[0], (const void*)g_W4Tu, BT_BYTES, barFull0);
        MBAR_EXPECT_TX(barFull1, BT_BYTES);
        bulk_g2s(bAddr[1], (const void*)(g_W4Tu + BT_UINTS), BT_BYTES, barFull1);
        MBAR_EXPECT_TX(barW, W23P_BYTES);
        bulk_g2s(smem_base, (const void*)g_W23pu, W23P_BYTES, barW);
    }

    // ---- small loads ----
    for (int i = t; i < 384; i += 256) {
        int p = i / 3, c = i - p * 3;
        xs[c * 128 + p] = (p0 + p < n) ? x[(size_t)(p0 + p) * 3 + c] : 0.f;
    }
    if (t < 192) w1s[t] = g_W1f[t];
    if (t < 64)  b1s[t] = g_b1f[t];
    if (t < 128) b23s[t] = g_b23f[t];
    if (t < 128) {
        int p = p0 + t;
        sb[t] = (p < n) ? batch[p] : -1;
    }
    __syncthreads();

    // ---- phase A: h3 = relu(h1 @ W23 + b23); h1 in regs; fp16 mma --------------
    {
        float xr[8][3];
        #pragma unroll
        for (int mbk = 0; mbk < 4; mbk++)
            #pragma unroll
            for (int j = 0; j < 2; j++) {
                int row = mhalf * 64 + mbk * 16 + r0 + 8 * j;
                xr[mbk * 2 + j][0] = xs[row];
                xr[mbk * 2 + j][1] = xs[128 + row];
                xr[mbk * 2 + j][2] = xs[256 + row];
            }

        MBAR_WAIT(barW, 0);       // W23p ready (in As overlay)
        float acc[4][4][4];
        #pragma unroll
        for (int i = 0; i < 4; i++)
            #pragma unroll
            for (int j = 0; j < 4; j++)
                #pragma unroll
                for (int r = 0; r < 4; r++) acc[i][j][r] = 0.f;

        const uint2* Wp = (const uint2*)sm;   // overlay in As region
        #pragma unroll 1
        for (int k16 = 0; k16 < 4; k16++) {
            int kb = k16 * 16;
            int ks[4] = { kb + 2 * kq, kb + 2 * kq + 1, kb + 2 * kq + 8, kb + 2 * kq + 9 };
            float wv[4][4];
            #pragma unroll
            for (int q = 0; q < 4; q++) {
                wv[q][0] = w1s[ks[q]]; wv[q][1] = w1s[64 + ks[q]];
                wv[q][2] = w1s[128 + ks[q]]; wv[q][3] = b1s[ks[q]];
            }
            uint32_t a[4][4];
            #pragma unroll
            for (int mbk = 0; mbk < 4; mbk++) {
                float h[2][4];
                #pragma unroll
                for (int j = 0; j < 2; j++) {
                    const float* xv = xr[mbk * 2 + j];
                    #pragma unroll
                    for (int q = 0; q < 4; q++)
                        h[j][q] = fmaxf(fmaf(xv[0], wv[q][0],
                                   fmaf(xv[1], wv[q][1], fmaf(xv[2], wv[q][2], wv[q][3]))), 0.f);
                }
                a[mbk][0] = pack_h2(h[0][0], h[0][1]);
                a[mbk][1] = pack_h2(h[1][0], h[1][1]);
                a[mbk][2] = pack_h2(h[0][2], h[0][3]);
                a[mbk][3] = pack_h2(h[1][2], h[1][3]);
            }
            #pragma unroll
            for (int nbk = 0; nbk < 4; nbk++) {
                uint2 bv = Wp[(k16 * 4 + kq) * SLABB + nblk * 32 + nbk * 8 + r0];
                #pragma unroll
                for (int mbk = 0; mbk < 4; mbk++)
                    mma_f16(acc[mbk][nbk], a[mbk], bv.x, bv.y);
            }
        }
        __syncthreads();   // ALL warps done reading W23p overlay before As writes

        // epilogue: bias + relu -> half2, write As (conflict-free)
        #pragma unroll
        for (int mbk = 0; mbk < 4; mbk++) {
            int ra = mhalf * 64 + mbk * 16 + r0;
            #pragma unroll
            for (int nbk = 0; nbk < 4; nbk++) {
                int c0 = nblk * 32 + nbk * 8 + kq * 2;
                float bb0 = b23s[c0], bb1 = b23s[c0 + 1];
                int cp = c0 >> 1;
                Asu[ra * 68 + cp] = pack_h2(fmaxf(acc[mbk][nbk][0] + bb0, 0.f),
                                            fmaxf(acc[mbk][nbk][1] + bb1, 0.f));
                Asu[(ra + 8) * 68 + cp] = pack_h2(fmaxf(acc[mbk][nbk][2] + bb0, 0.f),
                                                  fmaxf(acc[mbk][nbk][3] + bb1, 0.f));
            }
        }
    }
    __syncthreads();          // As visible to all warps

    // ldmatrix per-lane addresses: lane l serves matrix (l>>3), local row (l&7)
    uint32_t aBase[4];
    {
        int mm = lane >> 3, ii = lane & 7;
        #pragma unroll
        for (int mbk = 0; mbk < 4; mbk++) {
            int row = mhalf * 64 + mbk * 16 + (mm & 1) * 8 + ii;
            aBase[mbk] = smem_base + (row * 68 + (mm >> 1) * 4) * 4;
        }
    }

    // ---- phase B: 8 N-tiles of 128 cols, fp16 mma, double-buffered -------------
    bool fast = (sb[0] >= 0) && (sb[0] == sb[127]);
    unsigned* outg = fast ? &out_enc[(size_t)sb[0] * 1024] : out_enc;

    #pragma unroll 1
    for (int nt = 0; nt < 8; nt++) {
        int buf = nt & 1;
        uint32_t barFull = buf ? barFull1 : barFull0;
        int parity = (nt >> 1) & 1;
        MBAR_WAIT(barFull, parity);
        const uint2* Bp = (const uint2*)Bbuf[buf];

        float acc[4][4][4];
        #pragma unroll
        for (int i = 0; i < 4; i++)
            #pragma unroll
            for (int q = 0; q < 4; q++)
                #pragma unroll
                for (int r = 0; r < 4; r++) acc[i][q][r] = 0.f;

        #pragma unroll 2
        for (int k16 = 0; k16 < 8; k16++) {
            uint32_t a[4][4];
            #pragma unroll
            for (int mbk = 0; mbk < 4; mbk++)
                ldsm_x4(a[mbk], aBase[mbk] + k16 * 32);
            #pragma unroll
            for (int nbk = 0; nbk < 4; nbk++) {
                uint2 bv = Bp[(k16 * 4 + kq) * SLABB + nblk * 32 + nbk * 8 + r0];
                #pragma unroll
                for (int mbk = 0; mbk < 4; mbk++)
                    mma_f16(acc[mbk][nbk], a[mbk], bv.x, bv.y);
            }
        }
        __syncthreads();   // all reads of B[buf] complete

        int n0 = nt * 128;
        if (fast) {
            if (t == 0 && nt + 2 < 8) {     // prefetch immediately after join
                FENCE_ASYNC_SHARED();
                MBAR_EXPECT_TX(barFull, BT_BYTES);
                bulk_g2s(bAddr[buf], (const void*)(g_W4Tu + (size_t)(nt + 2) * BT_UINTS),
                         BT_BYTES, barFull);
            }
            #pragma unroll
            for (int nbk = 0; nbk < 4; nbk++) {
                float e = fmaxf(acc[0][nbk][0], acc[0][nbk][2]);
                float o = fmaxf(acc[0][nbk][1], acc[0][nbk][3]);
                #pragma unroll
                for (int mbk = 1; mbk < 4; mbk++) {
                    e = fmaxf(e, fmaxf(acc[mbk][nbk][0], acc[mbk][nbk][2]));
                    o = fmaxf(o, fmaxf(acc[mbk][nbk][1], acc[mbk][nbk][3]));
                }
                #pragma unroll
                for (int d = 4; d <= 16; d <<= 1) {
                    e = fmaxf(e, __shfl_xor_sync(0xffffffffu, e, d));
                    o = fmaxf(o, __shfl_xor_sync(0xffffffffu, o, d));
                }
                if (r0 == 0) {
                    int c = n0 + nblk * 32 + nbk * 8 + kq * 2;
                    atomicMax(&outg[c], encf(e));
                    atomicMax(&outg[c + 1], encf(o));
                }
            }
        } else {
            // slow path: stage 64 rows at a time into freed B[buf] (pitch 132)
            float* Cs = Bbuf[buf];
            #pragma unroll 1
            for (int h = 0; h < 2; h++) {
                if (mhalf == h) {
                    #pragma unroll
                    for (int mbk = 0; mbk < 4; mbk++) {
                        int rl = mbk * 16 + r0;
                        #pragma unroll
                        for (int nbk = 0; nbk < 4; nbk++) {
                            int c0 = nblk * 32 + nbk * 8 + kq * 2;
                            *(float2*)&Cs[rl * 132 + c0] =
                                make_float2(acc[mbk][nbk][0], acc[mbk][nbk][1]);
                            *(float2*)&Cs[(rl + 8) * 132 + c0] =
                                make_float2(acc[mbk][nbk][2], acc[mbk][nbk][3]);
                        }
                    }
                }
                __syncthreads();
                {   // 256 threads: col = t&127, quarter = t>>7 scans 32 rows
                    int col = t & 127, qh = t >> 7;
                    int cur = -2; float best = 0.f;
                    unsigned* obase = &out_enc[n0 + col];
                    int mbase = h * 64 + qh * 32;
                    for (int m = 0; m < 32; m++) {
                        int g2 = sb[mbase + m];
                        float v = Cs[(qh * 32 + m) * 132 + col];
                        if (g2 != cur) {
                            if (cur >= 0) atomicMax(obase + (size_t)cur * 1024, encf(best));
                            cur = g2; best = v;
                        } else best = fmaxf(best, v);
                    }
                    if (cur >= 0) atomicMax(obase + (size_t)cur * 1024, encf(best));
                }
                __syncthreads();
            }
            if (t == 0 && nt + 2 < 8) {
                FENCE_ASYNC_SHARED();
                MBAR_EXPECT_TX(barFull, BT_BYTES);
                bulk_g2s(bAddr[buf], (const void*)(g_W4Tu + (size_t)(nt + 2) * BT_UINTS),
                         BT_BYTES, barFull);
            }
        }
    }
}

// ---------------- decode --------------------------------------------------------
__global__ void decode_out(float* out, const float* __restrict__ b4, int total) {
    int i = blockIdx.x * 256 + threadIdx.x;
    if (i < total) {
        unsigned u = ((unsigned*)out)[i];
        unsigned d = (u & 0x80000000u) ? (u ^ 0x80000000u) : ~u;
        out[i] = __uint_as_float(d) + b4[i & 1023];
    }
}

// ---------------- launch -------------------------------------------------------
extern "C" void kernel_launch(void* const* d_in, const int* in_sizes, int n_in,
                              void* d_out, int out_size)
{
    const float* x     = (const float*)d_in[0];
    const int*   batch = (const int*)  d_in[1];
    const float* W1  = (const float*)d_in[2];
    const float* b1  = (const float*)d_in[3];
    const float* g1  = (const float*)d_in[4];
    const float* be1 = (const float*)d_in[5];
    const float* m1  = (const float*)d_in[6];
    const float* v1  = (const float*)d_in[7];
    const float* W2  = (const float*)d_in[8];
    const float* b2  = (const float*)d_in[9];
    const float* W3  = (const float*)d_in[10];
    const float* b3  = (const float*)d_in[11];
    const float* g3  = (const float*)d_in[12];
    const float* be3 = (const float*)d_in[13];
    const float* m3  = (const float*)d_in[14];
    const float* v3  = (const float*)d_in[15];
    const float* W4  = (const float*)d_in[16];
    const float* b4  = (const float*)d_in[17];

    int n  = in_sizes[0] / 3;
    int NT = (n + 127) / 128;

    size_t smB = 106000;   // -> 2 CTAs/SM
    cudaFuncSetAttribute(fused_kernel, cudaFuncAttributeMaxDynamicSharedMemorySize, (int)smB);

    prep_kernel<<<1, 128>>>(W1, b1, g1, be1, m1, v1, W2, b2, W3, b3, g3, be3, m3, v3);

    int initN = out_size > 65536 ? out_size : 65536;
    w4t_init_kernel<<<(initN + 255) / 256, 256>>>(W4, (unsigned*)d_out, out_size);

    fused_kernel<<<NT, 256, smB>>>(x, batch, (unsigned*)d_out, n);

    decode_out<<<(out_size + 255) / 256, 256>>>((float*)d_out, b4, out_size);
}